// round 17
// baseline (speedup 1.0000x reference)
#include <cuda_runtime.h>
#include <cuda_fp16.h>
#include <cstdint>

#define GD 128
#define GRID_VOL (GD*GD*GD)
#define CCH 64
#define KVOL 125
#define NMAX 200704
#define GUARD 16
#define NTILES 784
#define KSLOT 64              // slots per (tile,k): mean ~24.4; overflow P ~ e^-25

// ---------------- static device scratch (no allocations allowed) -------------
__device__ __align__(16) int g_idx_map[GRID_VOL + 2*GUARD];
__device__ int      g_lin[NMAX];
__device__ __half2  g_feath2[NMAX * 32];          // feats f16, 128B/row
__device__ __half   g_Wfrag[KVOL * 4096];         // W in mma b-frag order
__device__ uint32_t g_bj[NTILES * KVOL * KSLOT];  // per-(tile,k) neighbor rows
__device__ uint8_t  g_bil[NTILES * KVOL * KSLOT]; // per-(tile,k) local out row
__device__ int      g_kcnt[NTILES * KVOL];
__device__ float    g_sum[CCH], g_sumsq[CCH], g_scale[CCH], g_shift[CCH];

__device__ __forceinline__ uint32_t smem_u32(const void* p) {
    uint32_t a;
    asm("{ .reg .u64 t; cvta.to.shared.u64 t, %1; cvt.u32.u64 %0, t; }"
        : "=r"(a) : "l"(p));
    return a;
}
#define SW128(o) ((o) ^ (((o) >> 3) & 0x70))

// ---------------- setup kernels ----------------------------------------------
__global__ void init_kernel() {
    int i = blockIdx.x * blockDim.x + threadIdx.x;
    int stride = gridDim.x * blockDim.x;
    for (int p = i; p < GRID_VOL + 2*GUARD; p += stride) g_idx_map[p] = -1;
    for (int p = i; p < NTILES * KVOL; p += stride) g_kcnt[p] = 0;
    if (i < CCH) { g_sum[i] = 0.f; g_sumsq[i] = 0.f; }
}

__global__ void build_hash_kernel(const int* __restrict__ coords, int N) {
    int i = blockIdx.x * blockDim.x + threadIdx.x;
    if (i < N) {
        int z = coords[3*i], y = coords[3*i+1], x = coords[3*i+2];
        int lin = (z << 14) + (y << 7) + x;
        g_lin[i] = lin;
        g_idx_map[lin + GUARD] = i;
    }
}

__global__ void fcvt_kernel(const float* __restrict__ feats, int n2) {
    int i = blockIdx.x * blockDim.x + threadIdx.x;
    int stride = gridDim.x * blockDim.x;
    const float2* src = (const float2*)feats;
    for (int q = i; q < n2; q += stride) {
        float2 v = src[q];
        g_feath2[q] = __floats2half2_rn(v.x, v.y);
    }
}

// W fragment order for mma.m16n8k16 B operand (validated R4/R8/R11/R15):
// per k: [nt(8)][lane(32)][ks(4)][4 halfs]
__global__ void wfrag_kernel(const float* __restrict__ Wt) {
    int id = blockIdx.x * blockDim.x + threadIdx.x;
    if (id < KVOL * 1024) {
        int k  = id >> 10;
        int r  = id & 1023;
        int nt = r >> 7;
        int l  = (r & 127) >> 2;
        int ks = r & 3;
        int ci = ks * 16 + (l & 3) * 2;
        int co = nt * 8 + (l >> 2);
        const float* wk = Wt + k * 4096;
        size_t off = ((size_t)(k * 8 + nt) * 32 + l) * 16 + ks * 4;
        g_Wfrag[off + 0] = __float2half(wk[(ci    ) * 64 + co]);
        g_Wfrag[off + 1] = __float2half(wk[(ci + 1) * 64 + co]);
        g_Wfrag[off + 2] = __float2half(wk[(ci + 8) * 64 + co]);
        g_Wfrag[off + 3] = __float2half(wk[(ci + 9) * 64 + co]);
    }
}

// ---------------- pair building: fixed-stride per-(tile,k) segments -----------
// grid: (ntiles, 25). Block = one (dz,dy) slice for one 256-row tile.
__global__ __launch_bounds__(256) void pairs_kernel(int N) {
    int slice = blockIdx.y;
    int dz = slice / 5 - 2, dy = slice % 5 - 2;
    int tile = blockIdx.x;
    int tid = threadIdx.x;
    int i = tile * 256 + tid;
    int lane = tid & 31;

    int lin = 0;
    bool rowok = (i < N);
    if (rowok) lin = g_lin[i];
    int z = lin >> 14, y = (lin >> 7) & 127, x = lin & 127;
    int zz = z + dz, yy = y + dy;
    rowok = rowok && ((unsigned)zz < 128u) && ((unsigned)yy < 128u);

    int cells[8];
    int sel = 0;
    if (rowok) {
        int lg = (zz << 14) + (yy << 7) + x + GUARD;
        int a0 = (lg - 2) & ~3;
        sel = (lg - 2) - a0;
        int4 c0 = __ldg((const int4*)&g_idx_map[a0]);
        int4 c1 = __ldg((const int4*)&g_idx_map[a0 + 4]);
        cells[0]=c0.x; cells[1]=c0.y; cells[2]=c0.z; cells[3]=c0.w;
        cells[4]=c1.x; cells[5]=c1.y; cells[6]=c1.z; cells[7]=c1.w;
    } else {
        #pragma unroll
        for (int q = 0; q < 8; q++) cells[q] = -1;
    }

    #pragma unroll
    for (int d = 0; d < 5; d++) {
        int k = slice * 5 + d;
        if (k == 62) continue;                    // center injected in conv
        int xn = x + d - 2;
        int j = -1;
        if (rowok && (unsigned)xn < 128u) {
            j = (sel == 0) ? cells[d]
              : (sel == 1) ? cells[d+1]
              : (sel == 2) ? cells[d+2]
              :              cells[d+3];
        }
        unsigned b = __ballot_sync(0xFFFFFFFFu, j >= 0);
        if (b) {
            int leader = __ffs(b) - 1;
            int pos = 0;
            if (lane == leader) pos = atomicAdd(&g_kcnt[tile * KVOL + k], __popc(b));
            pos = __shfl_sync(0xFFFFFFFFu, pos, leader);
            if (j >= 0) {
                int slot = pos + __popc(b & ((1u << lane) - 1u));
                if (slot < KSLOT) {
                    size_t o = (size_t)(tile * KVOL + k) * KSLOT + slot;
                    g_bj[o]  = (uint32_t)j;
                    g_bil[o] = (uint8_t)(tid & 255);
                }
            }
        }
    }
}

// ---------------- conv: output-tile-stationary GEMM, deep pipeline ------------
// Block = 256 output rows, 8 warps (warp w owns cols [8w, 8w+8)).
// Chunk = 32 gathered rows of one k. 4-buffer cp.async ring, depth-2 lookahead,
// index LDGs prefetched one iteration early, W frags prefetched one chunk
// early into registers. f32 accumulation in SMEM (race-free col split).
#define OFF_STG   69632u      // 4 x 4096 (1024-aligned)
#define OFF_DESC  86016u      // 256 u32
#define OFF_SCNT  87040u      // 125 int
#define OFF_SILC  87552u      // 4 x 32 int
#define OFF_SWS   88064u      // 4 int
#define OFF_SNC   88080u      // 1 int
#define SMEM_DYN  88192

__global__ __launch_bounds__(256, 2) void conv_kernel(float* __restrict__ hout, int N)
{
    extern __shared__ __align__(16) unsigned char dsm[];
    float*    accf = (float*)dsm;                 // 256 x 68 f32
    unsigned char* stg = dsm + OFF_STG;
    uint32_t* desc = (uint32_t*)(dsm + OFF_DESC);
    int*      scnt = (int*)(dsm + OFF_SCNT);
    int*      silc = (int*)(dsm + OFF_SILC);
    int*      sws  = (int*)(dsm + OFF_SWS);
    int*      snc  = (int*)(dsm + OFF_SNC);

    const int tid = threadIdx.x, lane = tid & 31, warp = tid >> 5;
    const int tile = blockIdx.x;
    const int m0 = tile * 256;
    const int nrows = min(256, N - m0);

    for (int p = tid; p < 256*68; p += 256) accf[p] = 0.f;

    // chunk counts per k + shfl-scan -> k-ordered chunk descriptors
    int m = 0, tot = 0;
    if (tid < KVOL) {
        tot = (tid == 62) ? nrows : min(__ldg(&g_kcnt[tile * KVOL + tid]), KSLOT);
        scnt[tid] = tot;
        m = (tot + 31) >> 5;
    }
    int v = m;
    #pragma unroll
    for (int off = 1; off < 32; off <<= 1) {
        int t = __shfl_up_sync(0xFFFFFFFFu, v, off);
        if (lane >= off) v += t;
    }
    if (tid < 128 && lane == 31) sws[warp] = v;
    __syncthreads();
    int prefix = 0;
    if (tid < 128) {
        #pragma unroll
        for (int w = 0; w < 4; w++) if (w < warp) prefix += sws[w];
    }
    int incl = v + prefix;
    if (tid == 127) snc[0] = incl;
    int cb = incl - m;
    for (int c2 = 0; c2 < m; c2++) {
        int n = min(32, tot - (c2 << 5));
        desc[cb + c2] = ((uint32_t)tid << 16) | ((uint32_t)c2 << 8) | (uint32_t)n;
    }
    __syncthreads();
    const int nc = snc[0];

    const int srow = tid >> 3, sq = tid & 7;      // staging: 8 threads/row
    const uint32_t stgu = smem_u32(stg);

    // prefetched per-thread staging state (one chunk's worth)
    int pf_il;
    const unsigned char* pf_src;

    #define LOAD_IDX(c)                                                         \
    {                                                                           \
        uint32_t dd = desc[(c)];                                                \
        int k2 = dd >> 16;                                                      \
        int st0 = (int)((dd >> 8) & 0xFFu) << 5;                                \
        int n = dd & 0xFFu;                                                     \
        pf_il = -1;                                                             \
        pf_src = (const unsigned char*)g_feath2;                                \
        if (srow < n) {                                                         \
            int j;                                                              \
            if (k2 == 62) { pf_il = st0 + srow; j = m0 + pf_il; }               \
            else {                                                              \
                size_t o = (size_t)(tile * KVOL + k2) * KSLOT + st0 + srow;     \
                pf_il = (int)__ldg(&g_bil[o]);                                  \
                j  = (int)__ldg(&g_bj[o]);                                      \
            }                                                                   \
            pf_src = (const unsigned char*)g_feath2 + (size_t)j * 128 + sq * 16;\
        }                                                                       \
    }

    #define ISSUE_CP(c)                                                         \
    {                                                                           \
        int buf = (c) & 3;                                                      \
        uint32_t dst = stgu + (uint32_t)buf * 4096u                             \
                     + SW128((uint32_t)(srow * 128 + sq * 16));                 \
        int ssz = (pf_il >= 0) ? 16 : 0;                                        \
        asm volatile("cp.async.cg.shared.global [%0], [%1], 16, %2;"            \
                     :: "r"(dst), "l"(pf_src), "r"(ssz) : "memory");            \
        if (sq == 0) silc[buf * 32 + srow] = pf_il;                             \
    }

    // prologue: stage chunks 0,1; prefetch idx for 2; W frags for chunk 0
    if (nc > 0) { LOAD_IDX(0); ISSUE_CP(0); }
    asm volatile("cp.async.commit_group;" ::: "memory");
    if (nc > 1) { LOAD_IDX(1); ISSUE_CP(1); }
    asm volatile("cp.async.commit_group;" ::: "memory");
    if (nc > 2) { LOAD_IDX(2); }

    uint4 b01n = make_uint4(0,0,0,0), b23n = make_uint4(0,0,0,0);
    if (nc > 0) {
        int k0 = desc[0] >> 16;
        const uint4* wb4 = (const uint4*)(g_Wfrag + (size_t)k0 * 4096);
        b01n = __ldg(wb4 + warp * 64 + lane * 2);
        b23n = __ldg(wb4 + warp * 64 + lane * 2 + 1);
    }

    const int c0col = warp * 8 + (lane & 3) * 2;
    const uint32_t r8 = (uint32_t)((lane & 7) + ((lane & 8) ? 8 : 0));
    const uint32_t cbx = (uint32_t)((lane & 16) ? 16 : 0);

    for (int c = 0; c < nc; c++) {
        if (c + 2 < nc) { ISSUE_CP(c + 2); }
        asm volatile("cp.async.commit_group;" ::: "memory");
        if (c + 3 < nc) { LOAD_IDX(c + 3); }
        asm volatile("cp.async.wait_group 2;" ::: "memory");
        __syncthreads();

        // W frags for this chunk were prefetched last iteration
        uint4 b01 = b01n, b23 = b23n;
        if (c + 1 < nc) {
            int k3 = desc[c + 1] >> 16;
            const uint4* wb4 = (const uint4*)(g_Wfrag + (size_t)k3 * 4096);
            b01n = __ldg(wb4 + warp * 64 + lane * 2);
            b23n = __ldg(wb4 + warp * 64 + lane * 2 + 1);
        }

        int n = desc[c] & 0xFFu;
        const uint32_t bu = stgu + (uint32_t)(c & 3) * 4096u;
        #pragma unroll
        for (int mt = 0; mt < 2; mt++) {
            if (mt * 16 >= n) break;
            float d0 = 0.f, d1 = 0.f, d2 = 0.f, d3 = 0.f;
            #pragma unroll
            for (int ks = 0; ks < 4; ks++) {
                uint32_t a0, a1, a2, a3;
                uint32_t ad = bu + SW128((uint32_t)(mt * 16) * 128u + r8 * 128u
                                         + (uint32_t)ks * 32u + cbx);
                asm volatile(
                    "ldmatrix.sync.aligned.m8n8.x4.shared.b16 {%0,%1,%2,%3}, [%4];"
                    : "=r"(a0), "=r"(a1), "=r"(a2), "=r"(a3) : "r"(ad));
                uint32_t bx = (ks == 0) ? b01.x : (ks == 1) ? b01.z
                            : (ks == 2) ? b23.x : b23.z;
                uint32_t by = (ks == 0) ? b01.y : (ks == 1) ? b01.w
                            : (ks == 2) ? b23.y : b23.w;
                asm volatile(
                    "mma.sync.aligned.m16n8k16.row.col.f32.f16.f16.f32 "
                    "{%0,%1,%2,%3}, {%4,%5,%6,%7}, {%8,%9}, {%0,%1,%2,%3};"
                    : "+f"(d0), "+f"(d1), "+f"(d2), "+f"(d3)
                    : "r"(a0), "r"(a1), "r"(a2), "r"(a3), "r"(bx), "r"(by));
            }
            int i0 = silc[(c & 3) * 32 + mt * 16 + (lane >> 2)];
            int i1 = silc[(c & 3) * 32 + mt * 16 + 8 + (lane >> 2)];
            if (i0 >= 0) {
                float2* p = (float2*)&accf[i0 * 68 + c0col];
                float2 vv = *p; vv.x += d0; vv.y += d1; *p = vv;
            }
            if (i1 >= 0) {
                float2* p = (float2*)&accf[i1 * 68 + c0col];
                float2 vv = *p; vv.x += d2; vv.y += d3; *p = vv;
            }
        }
    }

    __syncthreads();
    // epilogue 1: single coalesced write of the tile
    int h = tid & 1;
    for (int r = tid >> 1; r < nrows; r += 128) {
        const float4* src = (const float4*)&accf[r * 68 + h * 32];
        float4* dst = (float4*)(hout + (size_t)(m0 + r) * 64 + h * 32);
        #pragma unroll
        for (int q = 0; q < 8; q++) dst[q] = src[q];
    }

    // epilogue 2: fused BN partial sums (channel c = tid&63, 4 thr/channel)
    {
        float* sred = (float*)stg;                // reuse staging (post-loop)
        int c = tid & 63;
        int g = tid >> 6;
        float ps = 0.f, pq = 0.f;
        for (int r = g; r < nrows; r += 4) {
            float vv = accf[r * 68 + c];
            ps += vv; pq += vv * vv;
        }
        sred[g * 64 + c]       = ps;
        sred[256 + g * 64 + c] = pq;
        __syncthreads();
        if (g == 0) {
            float a  = sred[c] + sred[64 + c] + sred[128 + c] + sred[192 + c];
            float b2 = sred[256 + c] + sred[320 + c] + sred[384 + c] + sred[448 + c];
            asm volatile("red.global.add.f32 [%0], %1;"
                         :: "l"(&g_sum[c]),   "f"(a)  : "memory");
            asm volatile("red.global.add.f32 [%0], %1;"
                         :: "l"(&g_sumsq[c]), "f"(b2) : "memory");
        }
    }
}

// ---------------- BN finalize / normalize+ELU --------------------------------
__global__ void finalize_kernel(const float* __restrict__ gamma,
                                const float* __restrict__ beta, int N) {
    int c = threadIdx.x;
    if (c < CCH) {
        float inv  = 1.f / (float)N;
        float mean = g_sum[c] * inv;              // conv bias cancels in BN
        float var  = g_sumsq[c] * inv - mean * mean;
        float scv  = gamma[c] * rsqrtf(var + 1e-5f);
        g_scale[c] = scv;
        g_shift[c] = beta[c] - mean * scv;
    }
}

__global__ void norm_elu_kernel(float* __restrict__ out, int total4) {
    int i = blockIdx.x * blockDim.x + threadIdx.x;
    int stride = gridDim.x * blockDim.x;
    for (int q = i; q < total4; q += stride) {
        float4 v = ((float4*)out)[q];
        int cb2 = (q * 4) & 63;
        float x0 = v.x * g_scale[cb2]   + g_shift[cb2];
        float x1 = v.y * g_scale[cb2+1] + g_shift[cb2+1];
        float x2 = v.z * g_scale[cb2+2] + g_shift[cb2+2];
        float x3 = v.w * g_scale[cb2+3] + g_shift[cb2+3];
        float4 r;
        r.x = x0 > 0.f ? x0 : expm1f(x0);
        r.y = x1 > 0.f ? x1 : expm1f(x1);
        r.z = x2 > 0.f ? x2 : expm1f(x2);
        r.w = x3 > 0.f ? x3 : expm1f(x3);
        ((float4*)out)[q] = r;
    }
}

// ---------------- launch ------------------------------------------------------
extern "C" void kernel_launch(void* const* d_in, const int* in_sizes, int n_in,
                              void* d_out, int out_size) {
    const float* feats  = (const float*)d_in[0];
    const int*   coords = (const int*)  d_in[1];
    const float* Wt     = (const float*)d_in[2];
    const float* gamma  = (const float*)d_in[4];
    const float* beta   = (const float*)d_in[5];
    float* out = (float*)d_out;
    int N = in_sizes[0] / CCH;
    int ntiles = (N + 255) / 256;

    cudaFuncSetAttribute(conv_kernel,
                         cudaFuncAttributeMaxDynamicSharedMemorySize, SMEM_DYN);

    init_kernel<<<2048, 512>>>();
    build_hash_kernel<<<(N + 255) / 256, 256>>>(coords, N);
    fcvt_kernel<<<2048, 256>>>(feats, N * 32);
    wfrag_kernel<<<(KVOL * 1024 + 255) / 256, 256>>>(Wt);
    {
        dim3 pg(ntiles, 25);
        pairs_kernel<<<pg, 256>>>(N);
    }
    conv_kernel<<<ntiles, 256, SMEM_DYN>>>(out, N);
    finalize_kernel<<<1, 64>>>(gamma, beta, N);
    norm_elu_kernel<<<2048, 256>>>(out, (N * CCH) / 4);
}